// round 1
// baseline (speedup 1.0000x reference)
#include <cuda_runtime.h>
#include <cuda_bf16.h>

#define N_PEDS 4096
#define TOPK 4
#define THREADS 256
#define WARPS (THREADS / 32)
#define IPW 2                               /* pedestrians per warp */
#define I_PER_BLOCK (WARPS * IPW)           /* 16 */
#define NBLOCKS (N_PEDS / I_PER_BLOCK)      /* 256 */

__device__ __forceinline__ void ins4(float dd, int j, float d[4], int id[4]) {
    // strict < keeps earlier index first on exact ties (stable, matches top_k)
    if (dd < d[3]) {
        if (dd < d[2]) {
            d[3] = d[2]; id[3] = id[2];
            if (dd < d[1]) {
                d[2] = d[1]; id[2] = id[1];
                if (dd < d[0]) {
                    d[1] = d[0]; id[1] = id[0];
                    d[0] = dd; id[0] = j;
                } else {
                    d[1] = dd; id[1] = j;
                }
            } else {
                d[2] = dd; id[2] = j;
            }
        } else {
            d[3] = dd; id[3] = j;
        }
    }
}

__device__ __forceinline__ void finish_one(
    int i, float ix, float iy,
    float d[4], int id[4],
    int lane, int kk, int o,
    float w0, float w1, float w3, float w4, float cst,
    const float* __restrict__ obs1, const float* __restrict__ obs2,
    const float2* s_pos, float* __restrict__ out)
{
    // Warp merge: 4 rounds of composite-key (dist, idx) min-reduction.
    int nb = 0;
    #pragma unroll
    for (int r = 0; r < 4; r++) {
        unsigned long long mykey =
            ((unsigned long long)__float_as_uint(d[0]) << 32) | (unsigned)id[0];
        unsigned long long k = mykey;
        #pragma unroll
        for (int off = 16; off; off >>= 1) {
            unsigned long long other = __shfl_xor_sync(0xffffffffu, k, off);
            if (other < k) k = other;
        }
        if (kk == r) nb = (int)(k & 0xffffffffu);
        if (mykey == k) {  // exactly one lane matches (ids unique per lane)
            d[0] = d[1]; id[0] = id[1];
            d[1] = d[2]; id[1] = id[2];
            d[2] = d[3]; id[2] = id[3];
            d[3] = __int_as_float(0x7f800000);
        }
    }

    // Features for this lane's (neighbor kk, output channel o).
    float2 pj = s_pos[nb];
    float px = pj.x - ix;
    float py = pj.y - iy;
    float vjx = __ldg(&obs2[2 * nb])     - __ldg(&obs1[2 * nb]);
    float vjy = __ldg(&obs2[2 * nb + 1]) - __ldg(&obs1[2 * nb + 1]);
    float vix = __ldg(&obs2[2 * i])      - __ldg(&obs1[2 * i]);
    float viy = __ldg(&obs2[2 * i + 1])  - __ldg(&obs1[2 * i + 1]);
    float vx = vjx - vix;
    float vy = vjy - viy;

    float e = cst + w0 * px + w1 * py + w3 * vx + w4 * vy;
    out[i * 32 + lane] = fmaxf(e, 0.0f);   // coalesced 128B store per warp
}

__global__ __launch_bounds__(THREADS)
void nn_tag_pool_kernel(const float* __restrict__ obs1,
                        const float* __restrict__ obs2,
                        const float* __restrict__ W,
                        const float* __restrict__ b,
                        float* __restrict__ out)
{
    __shared__ float2 s_pos[N_PEDS];   // 32 KB

    const int tid = threadIdx.x;
    const float2* obs2v = (const float2*)obs2;
    #pragma unroll 4
    for (int j = tid; j < N_PEDS; j += THREADS)
        s_pos[j] = obs2v[j];
    __syncthreads();

    const int lane = tid & 31;
    const int warp = tid >> 5;
    const int i0 = blockIdx.x * I_PER_BLOCK + warp * IPW;
    const int i1 = i0 + 1;

    const float ax = s_pos[i0].x, ay = s_pos[i0].y;
    const float bx = s_pos[i1].x, by = s_pos[i1].y;

    const float INF = __int_as_float(0x7f800000);
    float dA[4] = {INF, INF, INF, INF};
    float dB[4] = {INF, INF, INF, INF};
    int   iA[4] = {0, 0, 0, 0};
    int   iB[4] = {0, 0, 0, 0};

    // Scan all candidates once; one LDS.64 amortized over IPW=2 pedestrians.
    for (int j = lane; j < N_PEDS; j += 32) {
        float2 p = s_pos[j];
        {
            // reproduce reference rounding exactly: dx*dx + dy*dy + 1.0
            float dx = __fadd_rn(p.x, -ax);
            float dy = __fadd_rn(p.y, -ay);
            float dd = __fadd_rn(__fadd_rn(__fmul_rn(dx, dx), __fmul_rn(dy, dy)), 1.0f);
            if (j != i0) ins4(dd, j, dA, iA);
        }
        {
            float dx = __fadd_rn(p.x, -bx);
            float dy = __fadd_rn(p.y, -by);
            float dd = __fadd_rn(__fadd_rn(__fmul_rn(dx, dx), __fmul_rn(dy, dy)), 1.0f);
            if (j != i1) ins4(dd, j, dB, iB);
        }
    }

    // Per-lane output assignment: lane = kk*8 + o over the [TOPK=4, 8] tile.
    const int o  = lane & 7;
    const int kk = lane >> 3;
    const float w0 = __ldg(&W[o * 6 + 0]);
    const float w1 = __ldg(&W[o * 6 + 1]);
    const float w2 = __ldg(&W[o * 6 + 2]);
    const float w3 = __ldg(&W[o * 6 + 3]);
    const float w4 = __ldg(&W[o * 6 + 4]);
    const float w5 = __ldg(&W[o * 6 + 5]);
    const float cst = __ldg(&b[o]) + w2 + w5;   // tag features are constant 1

    finish_one(i0, ax, ay, dA, iA, lane, kk, o, w0, w1, w3, w4, cst,
               obs1, obs2, s_pos, out);
    finish_one(i1, bx, by, dB, iB, lane, kk, o, w0, w1, w3, w4, cst,
               obs1, obs2, s_pos, out);
}

extern "C" void kernel_launch(void* const* d_in, const int* in_sizes, int n_in,
                              void* d_out, int out_size)
{
    const float* obs1 = (const float*)d_in[0];
    const float* obs2 = (const float*)d_in[1];
    const float* W    = (const float*)d_in[2];
    const float* b    = (const float*)d_in[3];
    float* out = (float*)d_out;

    nn_tag_pool_kernel<<<NBLOCKS, THREADS>>>(obs1, obs2, W, b, out);
}